// round 9
// baseline (speedup 1.0000x reference)
#include <cuda_runtime.h>
#include <stdint.h>

// TorchNeighborList on GB300 — R8.
// R7 + rank-major idx writer: invert rank->t via sorted valid list (binary
// search once per 128-rank segment, incremental advance), write idx streams
// with aligned float4 stores. New k3b compacts mask -> d_sorted.

#define NA    1024
#define PCI   523776            // NA*(NA-1)/2
#define MAXB  256
#define CUT   5.0f
#define OUTB  1664
#define CTRB  64
#define P1B   (OUTB + CTRB)     // 1728
#define K1ZB  3072
#define SCANAB 432
#define K2ZB  512
#define SORTB 432
#define K3ZB  512
#define NWB   896               // writer blocks in k4 (229,376 threads)
#define K4ZB  512
// zero-fill slice boundaries in float4 units (total TWOP float4s = 28,310,528)
#define Z1    24000000
#define Z2    26000000
#define Z3    28000000

__device__ unsigned d_mask[442368];
__device__ int      d_wpre[442368];
__device__ int      d_bsums[512];
__device__ int      d_bpre[512];
__device__ int      d_atomCount[NA];
__device__ int      d_atomBase[NA];
__device__ unsigned d_bucket[NA * MAXB];
__device__ unsigned d_sorted[1 << 22];   // valid t2 list, globally sorted
__device__ int      d_Vh;
__device__ int      d_V;

__device__ __forceinline__ int rowstartC(int i) {
    return i * 1023 - (i * (i - 1)) / 2;
}

__device__ __forceinline__ void decodeCenter(int t2, int& i0, int& j0) {
    float q = (float)t2;
    float disc = __fsub_rn(1047552.25f, __fadd_rn(q, q));
    int i = (int)(1023.5f - __fsqrt_rn(disc));
    if (i < 0) i = 0;
    if (i > 1022) i = 1022;
    while (rowstartC(i + 1) <= t2) ++i;
    while (rowstartC(i) > t2) --i;
    i0 = i;
    j0 = t2 - rowstartC(i) + i + 1;
}

__device__ __forceinline__ void zeroSlice(float4* p, int lo, int hi,
                                          int g, int stride) {
    float4 z = make_float4(0.f, 0.f, 0.f, 0.f);
    for (int i = lo + g; i < hi; i += stride)
        __stcs(&p[i], z);
}

// ---- K1: pass1 + zero slice [0,Z1) ----
__global__ void k1(const float* __restrict__ pos, const float* __restrict__ box,
                   const int* __restrict__ shifts, long long P, long long TWOP,
                   float* __restrict__ out) {
    __shared__ float spx[NA], spy[NA], spz[NA];
    int tid = threadIdx.x;
    if (blockIdx.x >= P1B) {
        int g = (blockIdx.x - P1B) * 256 + tid;
        zeroSlice((float4*)(out + 2 * TWOP), 0, Z1, g, K1ZB * 256);
        return;
    }
    for (int k = tid; k < NA; k += 256) {
        spx[k] = pos[3 * k + 0];
        spy[k] = pos[3 * k + 1];
        spz[k] = pos[3 * k + 2];
    }
    __syncthreads();
    if (blockIdx.x < OUTB) {
        int rowBase = blockIdx.x * 8;
        #pragma unroll 1
        for (int rr = 0; rr < 8; rr++) {
            int row = rowBase + rr;
            int s = row >> 10, i = row & 1023;
            float s0 = (float)shifts[3 * s + 0];
            float s1 = (float)shifts[3 * s + 1];
            float s2 = (float)shifts[3 * s + 2];
            float svx = s0 * box[0] + s1 * box[3] + s2 * box[6];
            float svy = s0 * box[1] + s1 * box[4] + s2 * box[7];
            float svz = s0 * box[2] + s1 * box[5] + s2 * box[8];
            float pix = spx[i], piy = spy[i], piz = spz[i];
            int t2base = PCI + (row << 10);
            #pragma unroll
            for (int c = 0; c < 4; c++) {
                int j = c * 256 + tid;
                float dx = __fadd_rn(__fsub_rn(pix, spx[j]), svx);
                float dy = __fadd_rn(__fsub_rn(piy, spy[j]), svy);
                float dz = __fadd_rn(__fsub_rn(piz, spz[j]), svz);
                float r2 = __fadd_rn(__fadd_rn(__fmul_rn(dx, dx), __fmul_rn(dy, dy)),
                                     __fmul_rn(dz, dz));
                bool valid = __fsqrt_rn(r2) < CUT;
                unsigned b = __ballot_sync(0xFFFFFFFFu, valid);
                if ((tid & 31) == 0)
                    d_mask[(t2base >> 5) + c * 8 + (tid >> 5)] = b;
                if (valid) {
                    unsigned t2 = (unsigned)(t2base + j);
                    int sl = atomicAdd(&d_atomCount[i], 1);
                    if (sl < MAXB) d_bucket[i * MAXB + sl] = t2;
                    int s2a = atomicAdd(&d_atomCount[j], 1);
                    if (s2a < MAXB) d_bucket[j * MAXB + s2a] = t2 + (unsigned)P;
                }
            }
        }
    } else {
        int cb = blockIdx.x - OUTB;
        #pragma unroll 1
        for (int c = 0; c < 32; c++) {
            int t2 = cb * 8192 + c * 256 + tid;
            bool valid = false;
            int i0 = 0, j0 = 0;
            if (t2 < PCI) {
                decodeCenter(t2, i0, j0);
                float dx = __fsub_rn(spx[i0], spx[j0]);
                float dy = __fsub_rn(spy[i0], spy[j0]);
                float dz = __fsub_rn(spz[i0], spz[j0]);
                float r2 = __fadd_rn(__fadd_rn(__fmul_rn(dx, dx), __fmul_rn(dy, dy)),
                                     __fmul_rn(dz, dz));
                valid = __fsqrt_rn(r2) < CUT;
            }
            unsigned b = __ballot_sync(0xFFFFFFFFu, valid);
            int wb = cb * 256 + c * 8 + (tid >> 5);
            if ((tid & 31) == 0 && wb < (PCI >> 5))
                d_mask[wb] = b;
            if (valid) {
                int sl = atomicAdd(&d_atomCount[i0], 1);
                if (sl < MAXB) d_bucket[i0 * MAXB + sl] = (unsigned)t2;
                int s2a = atomicAdd(&d_atomCount[j0], 1);
                if (s2a < MAXB) d_bucket[j0 * MAXB + s2a] = (unsigned)(t2 + P);
            }
        }
    }
}

// ---- K2: scanA + zero slice [Z1,Z2) ----
__global__ void k2(int W, long long TWOP, float* __restrict__ out) {
    if (blockIdx.x >= SCANAB) {
        int g = (blockIdx.x - SCANAB) * 1024 + threadIdx.x;
        zeroSlice((float4*)(out + 2 * TWOP), Z1, Z2, g, K2ZB * 1024);
        return;
    }
    __shared__ int wsum[32];
    int tid = threadIdx.x, lane = tid & 31, wid = tid >> 5;
    int w = blockIdx.x * 1024 + tid;
    int v = (w < W) ? __popc(d_mask[w]) : 0;
    int x = v;
    #pragma unroll
    for (int o = 1; o < 32; o <<= 1) {
        int y = __shfl_up_sync(0xFFFFFFFFu, x, o);
        if (lane >= o) x += y;
    }
    if (lane == 31) wsum[wid] = x;
    __syncthreads();
    if (wid == 0) {
        int y = wsum[lane];
        #pragma unroll
        for (int o = 1; o < 32; o <<= 1) {
            int z = __shfl_up_sync(0xFFFFFFFFu, y, o);
            if (lane >= o) y += z;
        }
        wsum[lane] = y;
    }
    __syncthreads();
    int base = wid ? wsum[wid - 1] : 0;
    if (w < W) d_wpre[w] = base + x - v;
    if (tid == 0) d_bsums[blockIdx.x] = wsum[31];
}

// ---- K3: scanB ----
__global__ void k3(int nb) {
    __shared__ int wsum[32];
    int tid = threadIdx.x, lane = tid & 31, wid = tid >> 5;
    int v = (tid < nb) ? d_bsums[tid] : 0;
    int x = v;
    #pragma unroll
    for (int o = 1; o < 32; o <<= 1) {
        int y = __shfl_up_sync(0xFFFFFFFFu, x, o);
        if (lane >= o) x += y;
    }
    if (lane == 31) wsum[wid] = x;
    __syncthreads();
    if (wid == 0) {
        int y = wsum[lane];
        #pragma unroll
        for (int o = 1; o < 32; o <<= 1) {
            int z = __shfl_up_sync(0xFFFFFFFFu, y, o);
            if (lane >= o) y += z;
        }
        wsum[lane] = y;
    }
    __syncthreads();
    int base = wid ? wsum[wid - 1] : 0;
    if (tid < nb) d_bpre[tid] = base + x - v;
    if (tid == 0) { d_Vh = wsum[31]; d_V = 2 * wsum[31]; }
    __syncthreads();
    int a = d_atomCount[tid];
    int xa = a;
    #pragma unroll
    for (int o = 1; o < 32; o <<= 1) {
        int y = __shfl_up_sync(0xFFFFFFFFu, xa, o);
        if (lane >= o) xa += y;
    }
    __syncthreads();
    if (lane == 31) wsum[wid] = xa;
    __syncthreads();
    if (wid == 0) {
        int y = wsum[lane];
        #pragma unroll
        for (int o = 1; o < 32; o <<= 1) {
            int z = __shfl_up_sync(0xFFFFFFFFu, y, o);
            if (lane >= o) y += z;
        }
        wsum[lane] = y;
    }
    __syncthreads();
    int basea = wid ? wsum[wid - 1] : 0;
    d_atomBase[tid] = basea + xa - a;
}

// ---- K3b: compact mask -> sorted valid list + zero slice [Z2,Z3) ----
__global__ void k3b(int W, long long TWOP, float* __restrict__ out) {
    if (blockIdx.x >= SORTB) {
        int g = (blockIdx.x - SORTB) * 1024 + threadIdx.x;
        zeroSlice((float4*)(out + 2 * TWOP), Z2, Z3, g, K3ZB * 1024);
        return;
    }
    int w = blockIdx.x * 1024 + threadIdx.x;
    if (w < W) {
        unsigned word = d_mask[w];
        if (word) {
            int base = d_bpre[w >> 10] + d_wpre[w];
            unsigned t0 = (unsigned)w << 5;
            while (word) {
                int b = __ffs(word) - 1;
                d_sorted[base++] = t0 + b;
                word &= word - 1;
            }
        }
    }
}

// ---- rank-major segment writer ----
__device__ __forceinline__ void writeSeg(int start, int end, int base, bool swap,
                                         int Vh, float* __restrict__ out, int TWOP) {
    int m = start - base;
    int lo = 0, hi = Vh;
    while (lo < hi) {
        int mid = (lo + hi) >> 1;
        if ((int)d_sorted[mid] - mid > m) hi = mid; else lo = mid + 1;
    }
    int k = lo;
    int brk = (k < Vh) ? (int)d_sorted[k] - k : 0x7FFFFFFF;
    bool cinit = false;
    int i0 = 0, rs = 0, nxt = 0;
    for (int r = start; r < end; r += 4) {
        float a[4], bq[4];
        int cnt = end - r;
        if (cnt > 4) cnt = 4;
        #pragma unroll
        for (int e = 0; e < 4; e++) {
            if (e >= cnt) break;
            if (m >= brk) {
                do { k++; } while (k < Vh && (int)d_sorted[k] - k <= m);
                brk = (k < Vh) ? (int)d_sorted[k] - k : 0x7FFFFFFF;
            }
            int t = m + k;
            int bi, bj;
            if (t >= PCI) {
                unsigned u = (unsigned)(t - PCI);
                bi = (int)((u >> 10) & 1023u);
                bj = (int)(u & 1023u);
            } else {
                if (!cinit) {
                    int jd;
                    decodeCenter(t, i0, jd);
                    rs = rowstartC(i0);
                    nxt = rs + 1023 - i0;
                    cinit = true;
                }
                while (t >= nxt) { i0++; rs = nxt; nxt += 1023 - i0; }
                bi = i0;
                bj = t - rs + i0 + 1;
            }
            a[e] = (float)bi;
            bq[e] = (float)bj;
            m++;
        }
        if (cnt == 4 && ((r & 3) == 0)) {
            float4 v1 = swap ? make_float4(bq[0], bq[1], bq[2], bq[3])
                             : make_float4(a[0], a[1], a[2], a[3]);
            float4 v2 = swap ? make_float4(a[0], a[1], a[2], a[3])
                             : make_float4(bq[0], bq[1], bq[2], bq[3]);
            __stcs((float4*)(out + r), v1);
            __stcs((float4*)(out + TWOP + r), v2);
        } else {
            for (int e = 0; e < cnt; e++) {
                out[r + e] = swap ? bq[e] : a[e];
                out[TWOP + r + e] = swap ? a[e] : bq[e];
            }
        }
    }
}

// ---- K4: rank-major idx writer | valid scatter | zero tail [Z3,TWOP) ----
__global__ void k4(const float* __restrict__ box, const int* __restrict__ shifts,
                   long long P64, long long TWOP64, float* __restrict__ out) {
    __shared__ unsigned sb[MAXB];
    int b = blockIdx.x, tid = threadIdx.x;
    int P = (int)P64, TWOP = (int)TWOP64;
    if (b < NWB) {
        int Vh = d_Vh, V = 2 * Vh;
        int IH = P - Vh;
        int A1 = (V + 3) & ~3;
        int E1 = V + IH;
        int A2s = E1;
        int A2 = (A2s + 3) & ~3;
        int E2 = TWOP;
        int nSeg1 = (E1 - A1 + 127) >> 7;
        int nSeg2 = (E2 - A2 + 127) >> 7;
        int gtid = b * 256 + tid;
        if (gtid < nSeg1) {
            int start = A1 + (gtid << 7);
            int end = start + 128; if (end > E1) end = E1;
            writeSeg(start, end, V, false, Vh, out, TWOP);
        } else if (gtid < nSeg1 + nSeg2) {
            int seg = gtid - nSeg1;
            int start = A2 + (seg << 7);
            int end = start + 128; if (end > E2) end = E2;
            writeSeg(start, end, A2s, true, Vh, out, TWOP);
        } else if (gtid == nSeg1 + nSeg2) {
            if (A1 > V)  writeSeg(V, A1, V, false, Vh, out, TWOP);
            if (A2 > A2s) writeSeg(A2s, A2, A2s, true, Vh, out, TWOP);
        }
    } else if (b < NWB + NA) {
        int v = b - NWB;
        int c = d_atomCount[v];
        if (c > MAXB) c = MAXB;
        for (int k = tid; k < c; k += 256) sb[k] = d_bucket[v * MAXB + k];
        __syncthreads();
        if (tid == 0) d_atomCount[v] = 0;   // reset for next graph replay
        if (tid >= c) return;
        unsigned te = sb[tid];
        int rank = 0;
        for (int k = 0; k < c; k++) rank += (sb[k] < te) ? 1 : 0;
        int r = d_atomBase[v] + rank;

        int t = (int)te;
        bool second = t >= P;
        int t2 = second ? t - P : t;
        int i0, j0, s;
        if (t2 >= PCI) {
            unsigned u = (unsigned)(t2 - PCI);
            s = (int)(u >> 20);
            i0 = (int)((u >> 10) & 1023u);
            j0 = (int)(u & 1023u);
        } else {
            s = -1;
            decodeCenter(t2, i0, j0);
        }
        int bi = second ? j0 : i0;
        int bj = second ? i0 : j0;
        float o0 = 0.f, o1 = 0.f, o2 = 0.f;
        if (s >= 0) {
            float sgn = second ? 1.0f : -1.0f;
            float s0 = sgn * (float)shifts[3 * s + 0];
            float s1 = sgn * (float)shifts[3 * s + 1];
            float s2 = sgn * (float)shifts[3 * s + 2];
            o0 = s0 * box[0] + s1 * box[3] + s2 * box[6];
            o1 = s0 * box[1] + s1 * box[4] + s2 * box[7];
            o2 = s0 * box[2] + s1 * box[5] + s2 * box[8];
        }
        out[r] = (float)bi;
        out[TWOP + r] = (float)bj;
        long long ob = 2LL * TWOP + 3LL * r;
        out[ob + 0] = o0;
        out[ob + 1] = o1;
        out[ob + 2] = o2;
        out[5LL * TWOP + r] = 1.0f;
    } else {
        int g = (b - NWB - NA) * 256 + tid;
        zeroSlice((float4*)(out + 2 * TWOP64), Z3, TWOP, g, K4ZB * 256);
    }
}

extern "C" void kernel_launch(void* const* d_in, const int* in_sizes, int n_in,
                              void* d_out, int out_size) {
    const float* pos  = (const float*)d_in[0];
    const float* box  = (const float*)d_in[1];
    const int* shifts = (const int*)d_in[2];

    long long TWOP = (long long)out_size / 6;    // 28,310,528
    long long P = TWOP / 2;                      // 14,155,264
    int W = (int)(P / 32);                       // 442,352
    float* out = (float*)d_out;

    k1<<<P1B + K1ZB, 256>>>(pos, box, shifts, P, TWOP, out);
    k2<<<SCANAB + K2ZB, 1024>>>(W, TWOP, out);
    k3<<<1, 1024>>>(SCANAB);
    k3b<<<SORTB + K3ZB, 1024>>>(W, TWOP, out);
    k4<<<NWB + NA + K4ZB, 256>>>(box, shifts, P, TWOP, out);
}

// round 10
// speedup vs baseline: 1.8629x; 1.8629x over previous
#include <cuda_runtime.h>
#include <stdint.h>

// TorchNeighborList on GB300 — R9 = R7 + smem-staged float4 idx writer.
// A t-chunk's invalid elements occupy a contiguous rank range, so each block
// stages compacted (bi,bj) in smem and writes 4 contiguous streams with
// aligned float4 stores. before(t) is O(1) from bpre/wpre/popc.

#define NA    1024
#define PCI   523776            // NA*(NA-1)/2
#define MAXB  256
#define CUT   5.0f
#define OUTB  1664
#define CTRB  64
#define P1B   (OUTB + CTRB)     // 1728
#define K1ZB  3072
#define SCANAB 432
#define K2ZB  512
#define CH    2048              // t-chunk per idx block
#define NCH   6912              // ceil(P / CH)
#define K4ZB  512
#define Z1    25000000
#define Z2    27000000

__device__ unsigned d_mask[442368];
__device__ int      d_wpre[442368];
__device__ int      d_bsums[512];
__device__ int      d_bpre[512];
__device__ int      d_atomCount[NA];
__device__ int      d_atomBase[NA];
__device__ unsigned d_bucket[NA * MAXB];
__device__ int      d_Vh;
__device__ int      d_V;

__device__ __forceinline__ int rowstartC(int i) {
    return i * 1023 - (i * (i - 1)) / 2;
}

__device__ __forceinline__ void decodeCenter(int t2, int& i0, int& j0) {
    float q = (float)t2;
    float disc = __fsub_rn(1047552.25f, __fadd_rn(q, q));
    int i = (int)(1023.5f - __fsqrt_rn(disc));
    if (i < 0) i = 0;
    if (i > 1022) i = 1022;
    while (rowstartC(i + 1) <= t2) ++i;
    while (rowstartC(i) > t2) --i;
    i0 = i;
    j0 = t2 - rowstartC(i) + i + 1;
}

__device__ __forceinline__ void zeroSlice(float4* p, int lo, int hi,
                                          int g, int stride) {
    float4 z = make_float4(0.f, 0.f, 0.f, 0.f);
    for (int i = lo + g; i < hi; i += stride)
        __stcs(&p[i], z);
}

// ---- K1: pass1 + zero slice [0,Z1) ----
__global__ void k1(const float* __restrict__ pos, const float* __restrict__ box,
                   const int* __restrict__ shifts, long long P, long long TWOP,
                   float* __restrict__ out) {
    __shared__ float spx[NA], spy[NA], spz[NA];
    int tid = threadIdx.x;
    if (blockIdx.x >= P1B) {
        int g = (blockIdx.x - P1B) * 256 + tid;
        zeroSlice((float4*)(out + 2 * TWOP), 0, Z1, g, K1ZB * 256);
        return;
    }
    for (int k = tid; k < NA; k += 256) {
        spx[k] = pos[3 * k + 0];
        spy[k] = pos[3 * k + 1];
        spz[k] = pos[3 * k + 2];
    }
    __syncthreads();
    if (blockIdx.x < OUTB) {
        int rowBase = blockIdx.x * 8;
        #pragma unroll 1
        for (int rr = 0; rr < 8; rr++) {
            int row = rowBase + rr;
            int s = row >> 10, i = row & 1023;
            float s0 = (float)shifts[3 * s + 0];
            float s1 = (float)shifts[3 * s + 1];
            float s2 = (float)shifts[3 * s + 2];
            float svx = s0 * box[0] + s1 * box[3] + s2 * box[6];
            float svy = s0 * box[1] + s1 * box[4] + s2 * box[7];
            float svz = s0 * box[2] + s1 * box[5] + s2 * box[8];
            float pix = spx[i], piy = spy[i], piz = spz[i];
            int t2base = PCI + (row << 10);
            #pragma unroll
            for (int c = 0; c < 4; c++) {
                int j = c * 256 + tid;
                float dx = __fadd_rn(__fsub_rn(pix, spx[j]), svx);
                float dy = __fadd_rn(__fsub_rn(piy, spy[j]), svy);
                float dz = __fadd_rn(__fsub_rn(piz, spz[j]), svz);
                float r2 = __fadd_rn(__fadd_rn(__fmul_rn(dx, dx), __fmul_rn(dy, dy)),
                                     __fmul_rn(dz, dz));
                bool valid = __fsqrt_rn(r2) < CUT;
                unsigned b = __ballot_sync(0xFFFFFFFFu, valid);
                if ((tid & 31) == 0)
                    d_mask[(t2base >> 5) + c * 8 + (tid >> 5)] = b;
                if (valid) {
                    unsigned t2 = (unsigned)(t2base + j);
                    int sl = atomicAdd(&d_atomCount[i], 1);
                    if (sl < MAXB) d_bucket[i * MAXB + sl] = t2;
                    int s2a = atomicAdd(&d_atomCount[j], 1);
                    if (s2a < MAXB) d_bucket[j * MAXB + s2a] = t2 + (unsigned)P;
                }
            }
        }
    } else {
        int cb = blockIdx.x - OUTB;
        #pragma unroll 1
        for (int c = 0; c < 32; c++) {
            int t2 = cb * 8192 + c * 256 + tid;
            bool valid = false;
            int i0 = 0, j0 = 0;
            if (t2 < PCI) {
                decodeCenter(t2, i0, j0);
                float dx = __fsub_rn(spx[i0], spx[j0]);
                float dy = __fsub_rn(spy[i0], spy[j0]);
                float dz = __fsub_rn(spz[i0], spz[j0]);
                float r2 = __fadd_rn(__fadd_rn(__fmul_rn(dx, dx), __fmul_rn(dy, dy)),
                                     __fmul_rn(dz, dz));
                valid = __fsqrt_rn(r2) < CUT;
            }
            unsigned b = __ballot_sync(0xFFFFFFFFu, valid);
            int wb = cb * 256 + c * 8 + (tid >> 5);
            if ((tid & 31) == 0 && wb < (PCI >> 5))
                d_mask[wb] = b;
            if (valid) {
                int sl = atomicAdd(&d_atomCount[i0], 1);
                if (sl < MAXB) d_bucket[i0 * MAXB + sl] = (unsigned)t2;
                int s2a = atomicAdd(&d_atomCount[j0], 1);
                if (s2a < MAXB) d_bucket[j0 * MAXB + s2a] = (unsigned)(t2 + P);
            }
        }
    }
}

// ---- K2: scanA + zero slice [Z1,Z2) ----
__global__ void k2(int W, long long TWOP, float* __restrict__ out) {
    if (blockIdx.x >= SCANAB) {
        int g = (blockIdx.x - SCANAB) * 1024 + threadIdx.x;
        zeroSlice((float4*)(out + 2 * TWOP), Z1, Z2, g, K2ZB * 1024);
        return;
    }
    __shared__ int wsum[32];
    int tid = threadIdx.x, lane = tid & 31, wid = tid >> 5;
    int w = blockIdx.x * 1024 + tid;
    int v = (w < W) ? __popc(d_mask[w]) : 0;
    int x = v;
    #pragma unroll
    for (int o = 1; o < 32; o <<= 1) {
        int y = __shfl_up_sync(0xFFFFFFFFu, x, o);
        if (lane >= o) x += y;
    }
    if (lane == 31) wsum[wid] = x;
    __syncthreads();
    if (wid == 0) {
        int y = wsum[lane];
        #pragma unroll
        for (int o = 1; o < 32; o <<= 1) {
            int z = __shfl_up_sync(0xFFFFFFFFu, y, o);
            if (lane >= o) y += z;
        }
        wsum[lane] = y;
    }
    __syncthreads();
    int base = wid ? wsum[wid - 1] : 0;
    if (w < W) d_wpre[w] = base + x - v;
    if (tid == 0) d_bsums[blockIdx.x] = wsum[31];
}

// ---- K3: scanB ----
__global__ void k3(int nb) {
    __shared__ int wsum[32];
    int tid = threadIdx.x, lane = tid & 31, wid = tid >> 5;
    int v = (tid < nb) ? d_bsums[tid] : 0;
    int x = v;
    #pragma unroll
    for (int o = 1; o < 32; o <<= 1) {
        int y = __shfl_up_sync(0xFFFFFFFFu, x, o);
        if (lane >= o) x += y;
    }
    if (lane == 31) wsum[wid] = x;
    __syncthreads();
    if (wid == 0) {
        int y = wsum[lane];
        #pragma unroll
        for (int o = 1; o < 32; o <<= 1) {
            int z = __shfl_up_sync(0xFFFFFFFFu, y, o);
            if (lane >= o) y += z;
        }
        wsum[lane] = y;
    }
    __syncthreads();
    int base = wid ? wsum[wid - 1] : 0;
    if (tid < nb) d_bpre[tid] = base + x - v;
    if (tid == 0) { d_Vh = wsum[31]; d_V = 2 * wsum[31]; }
    __syncthreads();
    int a = d_atomCount[tid];
    int xa = a;
    #pragma unroll
    for (int o = 1; o < 32; o <<= 1) {
        int y = __shfl_up_sync(0xFFFFFFFFu, xa, o);
        if (lane >= o) xa += y;
    }
    __syncthreads();
    if (lane == 31) wsum[wid] = xa;
    __syncthreads();
    if (wid == 0) {
        int y = wsum[lane];
        #pragma unroll
        for (int o = 1; o < 32; o <<= 1) {
            int z = __shfl_up_sync(0xFFFFFFFFu, y, o);
            if (lane >= o) y += z;
        }
        wsum[lane] = y;
    }
    __syncthreads();
    int basea = wid ? wsum[wid - 1] : 0;
    d_atomBase[tid] = basea + xa - a;
}

// ---- cooperative contiguous range write: dst[0..n) = s[0..n), float4 body ----
__device__ __forceinline__ void writeRange(float* __restrict__ dst,
                                           const float* __restrict__ s,
                                           int n, int tid) {
    int head = (int)((4 - ((((uintptr_t)dst) >> 2) & 3)) & 3);
    if (head > n) head = n;
    if (tid < head) dst[tid] = s[tid];
    int n4 = (n - head) >> 2;
    const float* s2 = s + head;
    float4* d4 = (float4*)(dst + head);
    for (int i = tid; i < n4; i += 256) {
        float4 v = make_float4(s2[4 * i], s2[4 * i + 1], s2[4 * i + 2], s2[4 * i + 3]);
        __stcs(&d4[i], v);
    }
    int done = head + 4 * n4;
    int rem = n - done;
    if (tid < rem) dst[done + tid] = s[done + tid];
}

// ---- K4: staged idx chunks | valid scatter | zero tail [Z2,TWOP) ----
__global__ void k4(const float* __restrict__ box, const int* __restrict__ shifts,
                   long long P64, long long TWOP64, float* __restrict__ out) {
    __shared__ float smA[CH];
    __shared__ float smB[CH];
    int b = blockIdx.x, tid = threadIdx.x;
    int P = (int)P64, TWOP = (int)TWOP64;
    if (b < NCH) {
        int Vh = d_Vh, V = 2 * Vh;
        int roff = P - Vh;
        int t0 = b * CH;
        int tEnd = t0 + CH; if (tEnd > P) tEnd = P;
        int w0 = t0 >> 5;
        int before0 = d_bpre[w0 >> 10] + d_wpre[w0];
        int beforeEnd;
        if (tEnd == P) beforeEnd = Vh;
        else { int we = tEnd >> 5; beforeEnd = d_bpre[we >> 10] + d_wpre[we]; }
        int nInv = (tEnd - t0) - (beforeEnd - before0);

        int tStart = t0 + tid * 8;
        if (tStart < tEnd) {
            int w = tStart >> 5;
            unsigned word = d_mask[w];
            int bit0 = tStart & 31;
            int beforeT = d_bpre[w >> 10] + d_wpre[w] +
                          __popc(word & ((bit0 ? (1u << bit0) : 1u) - 1u));
            // (1u<<0)-1 == 0 anyway; expression avoids UB-free concerns
            beforeT = d_bpre[w >> 10] + d_wpre[w] + __popc(word & ((1u << bit0) - 1u));
            bool ci = false;
            int i0 = 0, rs = 0, nxt = 0;
            #pragma unroll 1
            for (int e = 0; e < 8; e++) {
                int t = tStart + e;
                if (t >= tEnd) break;
                int bit = bit0 + e;
                int vbit = (int)((word >> bit) & 1u);
                if (!vbit) {
                    int slot = (t - t0) - (beforeT - before0);
                    int bi, bj;
                    if (t >= PCI) {
                        unsigned u = (unsigned)(t - PCI);
                        bi = (int)((u >> 10) & 1023u);
                        bj = (int)(u & 1023u);
                    } else {
                        if (!ci) {
                            decodeCenter(t, i0, bj);
                            rs = rowstartC(i0);
                            nxt = rs + 1023 - i0;
                            ci = true;
                        } else {
                            while (t >= nxt) { i0++; rs = nxt; nxt += 1023 - i0; }
                            bj = t - rs + i0 + 1;
                        }
                        bi = i0;
                    }
                    smA[slot] = (float)bi;
                    smB[slot] = (float)bj;
                }
                beforeT += vbit;
            }
        }
        __syncthreads();
        int r0 = V + t0 - before0;
        writeRange(out + r0, smA, nInv, tid);                    // idx_i first half
        writeRange(out + TWOP + r0, smB, nInv, tid);             // idx_j first half
        writeRange(out + r0 + roff, smB, nInv, tid);             // idx_i second half
        writeRange(out + TWOP + r0 + roff, smA, nInv, tid);      // idx_j second half
    } else if (b < NCH + NA) {
        int v = b - NCH;
        unsigned* sb = (unsigned*)smA;
        int c = d_atomCount[v];
        if (c > MAXB) c = MAXB;
        for (int k = tid; k < c; k += 256) sb[k] = d_bucket[v * MAXB + k];
        __syncthreads();
        if (tid == 0) d_atomCount[v] = 0;   // reset for next graph replay
        if (tid >= c) return;
        unsigned te = sb[tid];
        int rank = 0;
        for (int k = 0; k < c; k++) rank += (sb[k] < te) ? 1 : 0;
        int r = d_atomBase[v] + rank;

        int t = (int)te;
        bool second = t >= P;
        int t2 = second ? t - P : t;
        int i0, j0, s;
        if (t2 >= PCI) {
            unsigned u = (unsigned)(t2 - PCI);
            s = (int)(u >> 20);
            i0 = (int)((u >> 10) & 1023u);
            j0 = (int)(u & 1023u);
        } else {
            s = -1;
            decodeCenter(t2, i0, j0);
        }
        int bi = second ? j0 : i0;
        int bj = second ? i0 : j0;
        float o0 = 0.f, o1 = 0.f, o2 = 0.f;
        if (s >= 0) {
            float sgn = second ? 1.0f : -1.0f;
            float s0 = sgn * (float)shifts[3 * s + 0];
            float s1 = sgn * (float)shifts[3 * s + 1];
            float s2 = sgn * (float)shifts[3 * s + 2];
            o0 = s0 * box[0] + s1 * box[3] + s2 * box[6];
            o1 = s0 * box[1] + s1 * box[4] + s2 * box[7];
            o2 = s0 * box[2] + s1 * box[5] + s2 * box[8];
        }
        out[r] = (float)bi;
        out[TWOP + r] = (float)bj;
        long long ob = 2LL * TWOP + 3LL * r;
        out[ob + 0] = o0;
        out[ob + 1] = o1;
        out[ob + 2] = o2;
        out[5LL * TWOP + r] = 1.0f;
    } else {
        int g = (b - NCH - NA) * 256 + tid;
        zeroSlice((float4*)(out + 2 * TWOP64), Z2, TWOP / 1, g, K4ZB * 256);
    }
}

extern "C" void kernel_launch(void* const* d_in, const int* in_sizes, int n_in,
                              void* d_out, int out_size) {
    const float* pos  = (const float*)d_in[0];
    const float* box  = (const float*)d_in[1];
    const int* shifts = (const int*)d_in[2];

    long long TWOP = (long long)out_size / 6;    // 28,310,528
    long long P = TWOP / 2;                      // 14,155,264
    int W = (int)(P / 32);                       // 442,352
    float* out = (float*)d_out;

    k1<<<P1B + K1ZB, 256>>>(pos, box, shifts, P, TWOP, out);
    k2<<<SCANAB + K2ZB, 1024>>>(W, TWOP, out);
    k3<<<1, 1024>>>(SCANAB);
    k4<<<NCH + NA + K4ZB, 256>>>(box, shifts, P, TWOP, out);
}